// round 2
// baseline (speedup 1.0000x reference)
#include <cuda_runtime.h>
#include <math.h>

#define B_TOTAL 131072
#define DIM     128
#define HID     256
#define NB      8
#define NL      4
#define KSEL    2
#define FIN     32
#define TB      32

// Scratch (no allocation allowed -> __device__ globals)
__device__ float g_h[(size_t)B_TOTAL * DIM];    // 64 MB hidden state
__device__ int   g_sel[NL * KSEL];              // routing decisions
__device__ float g_gfac[NL * KSEL][DIM];        // per-slot (1 + sigmoid(gate)*tf)

typedef unsigned long long u64;

__device__ __forceinline__ u64 pk2(float x, float y) {
    u64 r; asm("mov.b64 %0, {%1, %2};" : "=l"(r) : "f"(x), "f"(y)); return r;
}
__device__ __forceinline__ float2 up2(u64 v) {
    float2 r; asm("mov.b64 {%0, %1}, %2;" : "=f"(r.x), "=f"(r.y) : "l"(v)); return r;
}
__device__ __forceinline__ u64 ffma2(u64 a, u64 b, u64 c) {
    u64 d; asm("fma.rn.f32x2 %0, %1, %2, %3;" : "=l"(d) : "l"(a), "l"(b), "l"(c)); return d;
}
__device__ __forceinline__ float gelu_exact(float x) {
    return 0.5f * x * (1.0f + erff(x * 0.70710678118654752440f));
}
__device__ __forceinline__ float sigm(float x) { return 1.0f / (1.0f + expf(-x)); }

// ---------------------------------------------------------------------------
// 1) Input projection: h[b,d] = x[b,:]@proj_w[:,d] + proj_b[d] + pos[0,0,d]
// ---------------------------------------------------------------------------
__global__ void proj_kernel(const float* __restrict__ x, const float* __restrict__ pw,
                            const float* __restrict__ pb, const float* __restrict__ pos) {
    __shared__ float xs[2][FIN];
    int tid = threadIdx.x;                 // 256
    size_t row0 = (size_t)blockIdx.x * 2;
    if (tid < 2 * FIN)
        xs[tid / FIN][tid % FIN] = x[(row0 + tid / FIN) * FIN + (tid % FIN)];
    __syncthreads();
    int r = tid >> 7, d = tid & 127;
    float acc = pb[d] + pos[d];
#pragma unroll
    for (int k = 0; k < FIN; k++) acc += xs[r][k] * pw[k * DIM + d];
    g_h[(row0 + r) * DIM + d] = acc;
}

// ---------------------------------------------------------------------------
// 2) Pilot: run sample-0 trajectory through all layers; produce routing + gate
// ---------------------------------------------------------------------------
__global__ void pilot_kernel(const float* __restrict__ x, const float* __restrict__ pw,
                             const float* __restrict__ pb, const float* __restrict__ pos,
                             const float* __restrict__ sel_w, const float* __restrict__ sel_b,
                             const float* __restrict__ ln_s, const float* __restrict__ ln_b,
                             const float* __restrict__ w1, const float* __restrict__ b1,
                             const float* __restrict__ w2, const float* __restrict__ b2,
                             const float* __restrict__ gate, const float* __restrict__ tf) {
    __shared__ float h0[DIM], hn[DIM], tbuf[HID], fbuf[DIM];
    __shared__ float redA[64], redB[64];
    __shared__ float sc[NB];
    __shared__ int   seli[KSEL];
    __shared__ float s_mu, s_rstd;
    int tid = threadIdx.x;   // 256

    if (tid < DIM) {
        float acc = pb[tid] + pos[tid];
#pragma unroll
        for (int k = 0; k < FIN; k++) acc += x[k] * pw[k * DIM + tid];
        h0[tid] = acc;
    }
    __syncthreads();

    for (int l = 0; l < NL; l++) {
        // selector scores for sample 0
        if (tid < NB) {
            float s = sel_b[l * NB + tid];
            for (int d = 0; d < DIM; d++) s += h0[d] * sel_w[(l * DIM + d) * NB + tid];
            sc[tid] = sigm(s) * 0.6f + 0.2f;   // + PRIORITY*0.4
        }
        __syncthreads();
        if (tid == 0) {
            int i0 = 0; float v0 = -1e30f;
            for (int j = 0; j < NB; j++) if (sc[j] > v0) { v0 = sc[j]; i0 = j; }
            int i1 = -1; float v1 = -1e30f;
            for (int j = 0; j < NB; j++) { if (j == i0) continue; if (sc[j] > v1) { v1 = sc[j]; i1 = j; } }
            seli[0] = i0; seli[1] = i1;
            g_sel[l * KSEL + 0] = i0; g_sel[l * KSEL + 1] = i1;
        }
        __syncthreads();

        for (int k = 0; k < KSEL; k++) {
            int i = seli[k];
            size_t bo = (size_t)(l * NB + i);
            if (tid < DIM) {
                float fv = 1.0f + sigm(gate[bo * DIM + tid]) * tf[tid];
                fbuf[tid] = fv;
                g_gfac[l * KSEL + k][tid] = fv;
            }
            // LayerNorm stats
            if (tid < 64) {
                float a = h0[tid], b = h0[tid + 64];
                redA[tid] = a + b; redB[tid] = a * a + b * b;
            }
            __syncthreads();
            if (tid == 0) {
                float s = 0.f, q = 0.f;
                for (int j = 0; j < 64; j++) { s += redA[j]; q += redB[j]; }
                float mu = s * (1.0f / DIM);
                s_mu = mu;
                s_rstd = rsqrtf(q * (1.0f / DIM) - mu * mu + 1e-5f);
            }
            __syncthreads();
            if (tid < DIM)
                hn[tid] = (h0[tid] - s_mu) * s_rstd * ln_s[bo * DIM + tid] + ln_b[bo * DIM + tid];
            __syncthreads();
            // t = gelu(hn @ W1 + b1)
            {
                float acc = b1[bo * HID + tid];
                const float* W1 = w1 + bo * DIM * HID;
                for (int d = 0; d < DIM; d++) acc += hn[d] * W1[(size_t)d * HID + tid];
                tbuf[tid] = gelu_exact(acc);
            }
            __syncthreads();
            // z = t @ W2 + b2 ; h0 += 0.5 * z * f
            if (tid < DIM) {
                float acc = b2[bo * DIM + tid];
                const float* W2 = w2 + bo * HID * DIM;
                for (int j = 0; j < HID; j++) acc += tbuf[j] * W2[(size_t)j * DIM + tid];
                h0[tid] += 0.5f * acc * fbuf[tid];
            }
            __syncthreads();
        }
    }
}

// ---------------------------------------------------------------------------
// 3) Fused expert-block application over the batch (one launch per slot)
//    dyn smem: raw[32][128] | hn[32][128] | w[32*256] | t[32][256]  = 96 KB
// ---------------------------------------------------------------------------
__global__ void __launch_bounds__(256, 2)
block_apply(int slot, int layer,
            const float* __restrict__ ln_s, const float* __restrict__ ln_b,
            const float* __restrict__ w1, const float* __restrict__ b1,
            const float* __restrict__ w2, const float* __restrict__ b2) {
    extern __shared__ float sm[];
    float* s_raw = sm;                         // 32*128
    float* s_hn  = sm + TB * DIM;              // 32*128
    float* s_w   = sm + 2 * TB * DIM;          // 32*256
    float* s_t   = s_w + 32 * HID;             // 32*256

    int blk = g_sel[slot];
    size_t bo = (size_t)(layer * NB + blk);
    const float* W1 = w1 + bo * DIM * HID;
    const float* W2 = w2 + bo * HID * DIM;
    const float* B1 = b1 + bo * HID;
    const float* B2 = b2 + bo * DIM;
    const float* LS = ln_s + bo * DIM;
    const float* LB = ln_b + bo * DIM;

    int tid = threadIdx.x, lane = tid & 31, wid = tid >> 5;
    size_t row0 = (size_t)blockIdx.x * TB;

    // ---- load + LayerNorm (warp `wid` owns rows wid*4 .. wid*4+3) ----
#pragma unroll
    for (int rr = 0; rr < 4; rr++) {
        int r = wid * 4 + rr;
        float4 v = *(const float4*)&g_h[(row0 + r) * DIM + lane * 4];
        float s = v.x + v.y + v.z + v.w;
        float q = v.x * v.x + v.y * v.y + v.z * v.z + v.w * v.w;
#pragma unroll
        for (int o = 16; o > 0; o >>= 1) {
            s += __shfl_xor_sync(0xffffffffu, s, o);
            q += __shfl_xor_sync(0xffffffffu, q, o);
        }
        float mu = s * (1.0f / DIM);
        float rstd = rsqrtf(q * (1.0f / DIM) - mu * mu + 1e-5f);
        int d = lane * 4;
        float4 ls = *(const float4*)&LS[d];
        float4 lb = *(const float4*)&LB[d];
        float4 hn;
        hn.x = (v.x - mu) * rstd * ls.x + lb.x;
        hn.y = (v.y - mu) * rstd * ls.y + lb.y;
        hn.z = (v.z - mu) * rstd * ls.z + lb.z;
        hn.w = (v.w - mu) * rstd * ls.w + lb.w;
        *(float4*)&s_raw[r * DIM + d] = v;
        *(float4*)&s_hn[r * DIM + d] = hn;
    }
    __syncthreads();

    // ---- GEMM1: t[32,256] = hn[32,128] @ W1[128,256]  (4 rows x 8 cols / thread)
    int ty = wid;       // rows ty*4..
    int tx = lane;      // cols tx*8..
    u64 acc[4][4];
#pragma unroll
    for (int i = 0; i < 4; i++)
#pragma unroll
        for (int c = 0; c < 4; c++) acc[i][c] = 0ULL;

    for (int dc = 0; dc < DIM; dc += 32) {
        // stage W1[dc..dc+32)[:] -> s_w   (8192 floats, 8 float4/thread)
        const float4* src = (const float4*)(W1 + (size_t)dc * HID);
        float4* dst = (float4*)s_w;
#pragma unroll
        for (int u = 0; u < 8; u++) dst[tid + u * 256] = src[tid + u * 256];
        __syncthreads();
#pragma unroll
        for (int dd = 0; dd < 32; dd++) {
            const u64* wq = (const u64*)&s_w[dd * HID + tx * 8];
            u64 b0 = wq[0], b1q = wq[1], b2q = wq[2], b3q = wq[3];
#pragma unroll
            for (int i = 0; i < 4; i++) {
                float a = s_hn[(ty * 4 + i) * DIM + dc + dd];
                u64 aa = pk2(a, a);
                acc[i][0] = ffma2(aa, b0, acc[i][0]);
                acc[i][1] = ffma2(aa, b1q, acc[i][1]);
                acc[i][2] = ffma2(aa, b2q, acc[i][2]);
                acc[i][3] = ffma2(aa, b3q, acc[i][3]);
            }
        }
        __syncthreads();
    }
    // epilogue: + b1, gelu, store t
#pragma unroll
    for (int i = 0; i < 4; i++) {
        int r = ty * 4 + i;
#pragma unroll
        for (int c = 0; c < 4; c++) {
            float2 p = up2(acc[i][c]);
            int col = tx * 8 + c * 2;
            s_t[r * HID + col]     = gelu_exact(p.x + B1[col]);
            s_t[r * HID + col + 1] = gelu_exact(p.y + B1[col + 1]);
        }
    }
    __syncthreads();

    // ---- GEMM2: z[32,128] = t[32,256] @ W2[256,128]  (4 rows x 4 cols / thread)
    u64 acc2[4][2];
#pragma unroll
    for (int i = 0; i < 4; i++) { acc2[i][0] = 0ULL; acc2[i][1] = 0ULL; }

    for (int jc = 0; jc < HID; jc += 32) {
        const float4* src = (const float4*)(W2 + (size_t)jc * DIM);
        float4* dst = (float4*)s_w;
#pragma unroll
        for (int u = 0; u < 4; u++) dst[tid + u * 256] = src[tid + u * 256];
        __syncthreads();
#pragma unroll
        for (int jj = 0; jj < 32; jj++) {
            const u64* wq = (const u64*)&s_w[jj * DIM + tx * 4];
            u64 b0 = wq[0], b1q = wq[1];
#pragma unroll
            for (int i = 0; i < 4; i++) {
                float a = s_t[(ty * 4 + i) * HID + jc + jj];
                u64 aa = pk2(a, a);
                acc2[i][0] = ffma2(aa, b0, acc2[i][0]);
                acc2[i][1] = ffma2(aa, b1q, acc2[i][1]);
            }
        }
        __syncthreads();
    }
    // epilogue: z=(acc+b2)*f; h = raw + 0.5*z
    int c0 = tx * 4;
    float4 f4  = *(const float4*)&g_gfac[slot][c0];
    float4 b2v = *(const float4*)&B2[c0];
#pragma unroll
    for (int i = 0; i < 4; i++) {
        int r = ty * 4 + i;
        float2 pa = up2(acc2[i][0]);
        float2 pb = up2(acc2[i][1]);
        float4 raw = *(const float4*)&s_raw[r * DIM + c0];
        float4 o;
        o.x = raw.x + 0.5f * (pa.x + b2v.x) * f4.x;
        o.y = raw.y + 0.5f * (pa.y + b2v.y) * f4.y;
        o.z = raw.z + 0.5f * (pb.x + b2v.z) * f4.z;
        o.w = raw.w + 0.5f * (pb.y + b2v.w) * f4.w;
        *(float4*)&g_h[(row0 + r) * DIM + c0] = o;
    }
}

// ---------------------------------------------------------------------------
// 4) Classifier head + emit (logits first, then h) — one warp per row
// ---------------------------------------------------------------------------
__global__ void final_kernel(const float* __restrict__ cls_w, const float* __restrict__ cls_b,
                             float* __restrict__ out) {
    __shared__ float cw[DIM * 2];
    int tid = threadIdx.x;   // 128
    cw[tid] = cls_w[tid];
    cw[tid + 128] = cls_w[tid + 128];
    __syncthreads();
    int lane = tid & 31, w = tid >> 5;
    size_t row = (size_t)blockIdx.x * 4 + w;
    int d = lane * 4;
    float4 v = *(const float4*)&g_h[row * DIM + d];
    float a0 = v.x * cw[(d + 0) * 2] + v.y * cw[(d + 1) * 2] + v.z * cw[(d + 2) * 2] + v.w * cw[(d + 3) * 2];
    float a1 = v.x * cw[(d + 0) * 2 + 1] + v.y * cw[(d + 1) * 2 + 1] + v.z * cw[(d + 2) * 2 + 1] + v.w * cw[(d + 3) * 2 + 1];
#pragma unroll
    for (int o = 16; o > 0; o >>= 1) {
        a0 += __shfl_xor_sync(0xffffffffu, a0, o);
        a1 += __shfl_xor_sync(0xffffffffu, a1, o);
    }
    if (lane == 0) {
        out[row * 2]     = a0 + cls_b[0];
        out[row * 2 + 1] = a1 + cls_b[1];
    }
    *(float4*)&out[(size_t)B_TOTAL * 2 + row * DIM + d] = v;
}

// ---------------------------------------------------------------------------
extern "C" void kernel_launch(void* const* d_in, const int* in_sizes, int n_in,
                              void* d_out, int out_size) {
    const float* x      = (const float*)d_in[0];
    const float* proj_w = (const float*)d_in[1];
    const float* proj_b = (const float*)d_in[2];
    const float* pos    = (const float*)d_in[3];
    const float* sel_w  = (const float*)d_in[4];
    const float* sel_b  = (const float*)d_in[5];
    const float* ln_s   = (const float*)d_in[6];
    const float* ln_b   = (const float*)d_in[7];
    const float* w1     = (const float*)d_in[8];
    const float* b1     = (const float*)d_in[9];
    const float* w2     = (const float*)d_in[10];
    const float* b2     = (const float*)d_in[11];
    const float* gate   = (const float*)d_in[12];
    const float* cls_w  = (const float*)d_in[13];
    const float* cls_b  = (const float*)d_in[14];
    const float* tf     = (const float*)d_in[15];
    float* out = (float*)d_out;

    const int smem_bytes = (2 * TB * DIM + 32 * HID + TB * HID) * sizeof(float);  // 96 KB
    cudaFuncSetAttribute(block_apply, cudaFuncAttributeMaxDynamicSharedMemorySize, smem_bytes);

    proj_kernel<<<B_TOTAL / 2, 256>>>(x, proj_w, proj_b, pos);
    pilot_kernel<<<1, 256>>>(x, proj_w, proj_b, pos, sel_w, sel_b, ln_s, ln_b,
                             w1, b1, w2, b2, gate, tf);
    for (int s = 0; s < NL * KSEL; s++)
        block_apply<<<B_TOTAL / TB, 256, smem_bytes>>>(s, s / KSEL, ln_s, ln_b, w1, b1, w2, b2);
    final_kernel<<<B_TOTAL / 4, 128>>>(cls_w, cls_b, out);
}

// round 3
// speedup vs baseline: 1.3750x; 1.3750x over previous
#include <cuda_runtime.h>
#include <math.h>
#include <stdint.h>

#define B_TOTAL 131072
#define DIM     128
#define HID     256
#define NB      8
#define NL      4
#define KSEL    2
#define FIN     32
#define ROWS    128      // rows per CTA tile
#define LDH     132      // padded stride (floats) for 128-wide tiles

__device__ int   g_sel[NL * KSEL];
__device__ float g_gfac[NL * KSEL][DIM];

__device__ __forceinline__ float sigm(float x) { return 1.0f / (1.0f + expf(-x)); }
__device__ __forceinline__ float gelu_exact(float x) {
    return 0.5f * x * (1.0f + erff(x * 0.70710678118654752440f));
}
__device__ __forceinline__ uint32_t tf32cvt(float x) {
    uint32_t r; asm("cvt.rna.tf32.f32 %0, %1;" : "=r"(r) : "f"(x)); return r;
}
__device__ __forceinline__ void mma_tf32(float c[4], const uint32_t a[4],
                                         uint32_t b0, uint32_t b1) {
    asm("mma.sync.aligned.m16n8k8.row.col.f32.tf32.tf32.f32 "
        "{%0,%1,%2,%3},{%4,%5,%6,%7},{%8,%9},{%0,%1,%2,%3};"
        : "+f"(c[0]), "+f"(c[1]), "+f"(c[2]), "+f"(c[3])
        : "r"(a[0]), "r"(a[1]), "r"(a[2]), "r"(a[3]), "r"(b0), "r"(b1));
}

// ---------------------------------------------------------------------------
// Pilot: sample-0 trajectory -> routing decisions + gate factors (unchanged)
// ---------------------------------------------------------------------------
__global__ void pilot_kernel(const float* __restrict__ x, const float* __restrict__ pw,
                             const float* __restrict__ pb, const float* __restrict__ pos,
                             const float* __restrict__ sel_w, const float* __restrict__ sel_b,
                             const float* __restrict__ ln_s, const float* __restrict__ ln_b,
                             const float* __restrict__ w1, const float* __restrict__ b1,
                             const float* __restrict__ w2, const float* __restrict__ b2,
                             const float* __restrict__ gate, const float* __restrict__ tf) {
    __shared__ float h0[DIM], hn[DIM], tbuf[HID], fbuf[DIM];
    __shared__ float redA[64], redB[64];
    __shared__ float sc[NB];
    __shared__ int   seli[KSEL];
    __shared__ float s_mu, s_rstd;
    int tid = threadIdx.x;   // 256

    if (tid < DIM) {
        float acc = pb[tid] + pos[tid];
#pragma unroll
        for (int k = 0; k < FIN; k++) acc += x[k] * pw[k * DIM + tid];
        h0[tid] = acc;
    }
    __syncthreads();

    for (int l = 0; l < NL; l++) {
        if (tid < NB) {
            float s = sel_b[l * NB + tid];
            for (int d = 0; d < DIM; d++) s += h0[d] * sel_w[(l * DIM + d) * NB + tid];
            sc[tid] = sigm(s) * 0.6f + 0.2f;
        }
        __syncthreads();
        if (tid == 0) {
            int i0 = 0; float v0 = -1e30f;
            for (int j = 0; j < NB; j++) if (sc[j] > v0) { v0 = sc[j]; i0 = j; }
            int i1 = -1; float v1 = -1e30f;
            for (int j = 0; j < NB; j++) { if (j == i0) continue; if (sc[j] > v1) { v1 = sc[j]; i1 = j; } }
            seli[0] = i0; seli[1] = i1;
            g_sel[l * KSEL + 0] = i0; g_sel[l * KSEL + 1] = i1;
        }
        __syncthreads();

        for (int k = 0; k < KSEL; k++) {
            int i = seli[k];
            size_t bo = (size_t)(l * NB + i);
            if (tid < DIM) {
                float fv = 1.0f + sigm(gate[bo * DIM + tid]) * tf[tid];
                fbuf[tid] = fv;
                g_gfac[l * KSEL + k][tid] = fv;
            }
            if (tid < 64) {
                float a = h0[tid], b = h0[tid + 64];
                redA[tid] = a + b; redB[tid] = a * a + b * b;
            }
            __syncthreads();
            if (tid == 0) {
                float s = 0.f, q = 0.f;
                for (int j = 0; j < 64; j++) { s += redA[j]; q += redB[j]; }
                float mu = s * (1.0f / DIM);
                s_mu = mu;
                s_rstd = rsqrtf(q * (1.0f / DIM) - mu * mu + 1e-5f);
            }
            __syncthreads();
            if (tid < DIM)
                hn[tid] = (h0[tid] - s_mu) * s_rstd * ln_s[bo * DIM + tid] + ln_b[bo * DIM + tid];
            __syncthreads();
            {
                float acc = b1[bo * HID + tid];
                const float* W1 = w1 + bo * DIM * HID;
                for (int d = 0; d < DIM; d++) acc += hn[d] * W1[(size_t)d * HID + tid];
                tbuf[tid] = gelu_exact(acc);
            }
            __syncthreads();
            if (tid < DIM) {
                float acc = b2[bo * DIM + tid];
                const float* W2 = w2 + bo * HID * DIM;
                for (int j = 0; j < HID; j++) acc += tbuf[j] * W2[(size_t)j * DIM + tid];
                h0[tid] += 0.5f * acc * fbuf[tid];
            }
            __syncthreads();
        }
    }
}

// ---------------------------------------------------------------------------
// Stage a [32 x 128] fp32 weight chunk into b-fragment-paired tf32 layout:
// u64 s_wp[ks(4)][n8(16)][lane(32)] with low = W[ks*8 + lane%4][n8*8 + lane/4],
//                                       high = W[ks*8 + lane%4 + 4][same col]
// so each mma's B fragment is ONE conflict-free LDS.64.
// ---------------------------------------------------------------------------
__device__ __forceinline__ void stage_w(const float* __restrict__ W, int ldn,
                                        uint32_t* __restrict__ s_wp, int tid) {
    int wid = tid >> 5, lane = tid & 31;
#pragma unroll
    for (int r4 = 0; r4 < 4; r4++) {
        int kr = r4 * 8 + wid;
        float4 v = *(const float4*)(W + (size_t)kr * ldn + lane * 4);
        int ks = kr >> 3, kk = kr & 7, kq = kk & 3, hi = kk >> 2;
        float vv[4] = {v.x, v.y, v.z, v.w};
#pragma unroll
        for (int ci = 0; ci < 4; ci++) {
            int cc = lane * 4 + ci;
            int n8 = cc >> 3, nq = cc & 7;
            int fidx = (((ks * 16 + n8) * 32) + nq * 4 + kq) * 2 + hi;
            s_wp[fidx] = tf32cvt(vv[ci]);
        }
    }
}

// ---------------------------------------------------------------------------
// Fused: proj -> 8 expert blocks (tf32 mma) -> classifier. h resident in smem.
// ---------------------------------------------------------------------------
__global__ void __launch_bounds__(256, 1)
fused_kernel(const float* __restrict__ xg, const float* __restrict__ pw,
             const float* __restrict__ pb, const float* __restrict__ pos,
             const float* __restrict__ ln_s, const float* __restrict__ ln_b,
             const float* __restrict__ w1g, const float* __restrict__ b1g,
             const float* __restrict__ w2g, const float* __restrict__ b2g,
             const float* __restrict__ cls_w, const float* __restrict__ cls_b,
             float* __restrict__ out) {
    extern __shared__ float sm[];
    float*    s_h  = sm;                                   // [ROWS][LDH] fp32
    uint32_t* s_hn = (uint32_t*)(sm + ROWS * LDH);         // [ROWS][LDH] tf32
    uint32_t* s_t  = (uint32_t*)(sm + 2 * ROWS * LDH);     // [ROWS][LDH] tf32
    float*    s_w  = sm + 3 * ROWS * LDH;                  // 4608 floats stage/x

    int tid = threadIdx.x, lane = tid & 31, wid = tid >> 5;
    int wm = wid >> 1, wn = wid & 1;          // 4 x 2 warp tiling
    int g = lane >> 2, tg = lane & 3;         // mma group / thread-in-group
    int mrow = wm * 32;
    size_t row0 = (size_t)blockIdx.x * ROWS;

    // ================= input projection: h = x@pw + pb + pos =================
    {
        float* s_x  = s_w;            // [128][36]
        float* s_pw = (float*)s_t;    // [32][LDH]
        for (int i = tid; i < 1024; i += 256) {            // pw: 32*128 floats
            int r = i >> 5, c4 = i & 31;
            float4 v = *(const float4*)(pw + r * DIM + c4 * 4);
            *(float4*)&s_pw[r * LDH + c4 * 4] = v;
        }
        for (int i = tid; i < 1024; i += 256) {            // x tile: 128*32
            int r = i >> 3, c4 = i & 7;
            float4 v = *(const float4*)(xg + (row0 + r) * FIN + c4 * 4);
            *(float4*)&s_x[r * 36 + c4 * 4] = v;
        }
        __syncthreads();
        int pr = tid >> 1, ph = tid & 1;
#pragma unroll
        for (int c4 = 0; c4 < 16; c4++) {
            int col = ph * 64 + c4 * 4;
            float4 acc = *(const float4*)(pb + col);
            float4 po  = *(const float4*)(pos + col);
            acc.x += po.x; acc.y += po.y; acc.z += po.z; acc.w += po.w;
#pragma unroll
            for (int k = 0; k < FIN; k++) {
                float a = s_x[pr * 36 + k];
                float4 w = *(const float4*)&s_pw[k * LDH + col];
                acc.x += a * w.x; acc.y += a * w.y; acc.z += a * w.z; acc.w += a * w.w;
            }
            *(float4*)&s_h[pr * LDH + col] = acc;
        }
        __syncthreads();
    }

    // ============================ 8 expert slots ============================
    for (int slot = 0; slot < NL * KSEL; slot++) {
        int layer = slot >> 1;
        int blk = g_sel[slot];
        size_t bo = (size_t)(layer * NB + blk);
        const float* W1 = w1g + bo * DIM * HID;
        const float* W2 = w2g + bo * HID * DIM;
        const float* B1 = b1g + bo * HID;
        const float* B2 = b2g + bo * DIM;
        const float* LS = ln_s + bo * DIM;
        const float* LB = ln_b + bo * DIM;

        // ---- LayerNorm -> s_hn (tf32) ----
        {
            float4 ls4 = *(const float4*)(LS + lane * 4);
            float4 lb4 = *(const float4*)(LB + lane * 4);
#pragma unroll 4
            for (int rr = 0; rr < 16; rr++) {
                int r = wid * 16 + rr;
                float4 v = *(const float4*)&s_h[r * LDH + lane * 4];
                float s = v.x + v.y + v.z + v.w;
                float q = v.x * v.x + v.y * v.y + v.z * v.z + v.w * v.w;
#pragma unroll
                for (int o = 16; o > 0; o >>= 1) {
                    s += __shfl_xor_sync(0xffffffffu, s, o);
                    q += __shfl_xor_sync(0xffffffffu, q, o);
                }
                float mu = s * (1.0f / DIM);
                float rstd = rsqrtf(q * (1.0f / DIM) - mu * mu + 1e-5f);
                uint4 o4;
                o4.x = tf32cvt((v.x - mu) * rstd * ls4.x + lb4.x);
                o4.y = tf32cvt((v.y - mu) * rstd * ls4.y + lb4.y);
                o4.z = tf32cvt((v.z - mu) * rstd * ls4.z + lb4.z);
                o4.w = tf32cvt((v.w - mu) * rstd * ls4.w + lb4.w);
                *(uint4*)&s_hn[r * LDH + lane * 4] = o4;
            }
        }
        __syncthreads();

        float zacc[2][8][4];
#pragma unroll
        for (int mi = 0; mi < 2; mi++)
#pragma unroll
            for (int j = 0; j < 8; j++)
#pragma unroll
                for (int e = 0; e < 4; e++) zacc[mi][j][e] = 0.0f;

        for (int half = 0; half < 2; half++) {
            // ---------- GEMM1 half: c1 = hn @ W1[:, half*128 ..] ----------
            float c1[2][8][4];
#pragma unroll
            for (int mi = 0; mi < 2; mi++)
#pragma unroll
                for (int j = 0; j < 8; j++)
#pragma unroll
                    for (int e = 0; e < 4; e++) c1[mi][j][e] = 0.0f;

            for (int kc = 0; kc < 4; kc++) {
                __syncthreads();
                stage_w(W1 + (size_t)(kc * 32) * HID + half * 128, HID, (uint32_t*)s_w, tid);
                __syncthreads();
#pragma unroll
                for (int ks = 0; ks < 4; ks++) {
                    int k0 = kc * 32 + ks * 8;
                    uint32_t a[2][4];
#pragma unroll
                    for (int mi = 0; mi < 2; mi++) {
                        int r = mrow + mi * 16 + g;
                        a[mi][0] = s_hn[r * LDH + k0 + tg];
                        a[mi][1] = s_hn[(r + 8) * LDH + k0 + tg];
                        a[mi][2] = s_hn[r * LDH + k0 + tg + 4];
                        a[mi][3] = s_hn[(r + 8) * LDH + k0 + tg + 4];
                    }
                    const unsigned long long* bp =
                        (const unsigned long long*)s_w + (ks * 16 + wn * 8) * 32 + lane;
#pragma unroll
                    for (int j = 0; j < 8; j++) {
                        unsigned long long b = bp[j * 32];
                        uint32_t b0 = (uint32_t)b, b1 = (uint32_t)(b >> 32);
                        mma_tf32(c1[0][j], a[0], b0, b1);
                        mma_tf32(c1[1][j], a[1], b0, b1);
                    }
                }
            }
            __syncthreads();
            // ---- +b1, GELU, -> s_t (tf32) ----
#pragma unroll
            for (int mi = 0; mi < 2; mi++)
#pragma unroll
                for (int j = 0; j < 8; j++) {
                    int col = wn * 64 + j * 8 + tg * 2;
                    float2 bb = *(const float2*)(B1 + half * 128 + col);
                    int r = mrow + mi * 16 + g;
                    float t0 = gelu_exact(c1[mi][j][0] + bb.x);
                    float t1 = gelu_exact(c1[mi][j][1] + bb.y);
                    unsigned long long p =
                        (unsigned long long)tf32cvt(t0) | ((unsigned long long)tf32cvt(t1) << 32);
                    *(unsigned long long*)&s_t[r * LDH + col] = p;
                    t0 = gelu_exact(c1[mi][j][2] + bb.x);
                    t1 = gelu_exact(c1[mi][j][3] + bb.y);
                    p = (unsigned long long)tf32cvt(t0) | ((unsigned long long)tf32cvt(t1) << 32);
                    *(unsigned long long*)&s_t[(r + 8) * LDH + col] = p;
                }
            __syncthreads();

            // ---------- GEMM2 partial: zacc += t_half @ W2[half*128 ..] ----------
            for (int kc = 0; kc < 4; kc++) {
                __syncthreads();
                stage_w(W2 + (size_t)(half * 128 + kc * 32) * DIM, DIM, (uint32_t*)s_w, tid);
                __syncthreads();
#pragma unroll
                for (int ks = 0; ks < 4; ks++) {
                    int k0 = kc * 32 + ks * 8;
                    uint32_t a[2][4];
#pragma unroll
                    for (int mi = 0; mi < 2; mi++) {
                        int r = mrow + mi * 16 + g;
                        a[mi][0] = s_t[r * LDH + k0 + tg];
                        a[mi][1] = s_t[(r + 8) * LDH + k0 + tg];
                        a[mi][2] = s_t[r * LDH + k0 + tg + 4];
                        a[mi][3] = s_t[(r + 8) * LDH + k0 + tg + 4];
                    }
                    const unsigned long long* bp =
                        (const unsigned long long*)s_w + (ks * 16 + wn * 8) * 32 + lane;
#pragma unroll
                    for (int j = 0; j < 8; j++) {
                        unsigned long long b = bp[j * 32];
                        uint32_t b0 = (uint32_t)b, b1 = (uint32_t)(b >> 32);
                        mma_tf32(zacc[0][j], a[0], b0, b1);
                        mma_tf32(zacc[1][j], a[1], b0, b1);
                    }
                }
            }
            __syncthreads();
        }

        // ---- residual epilogue: h += 0.5 * (z + b2) * gfac ----
#pragma unroll
        for (int mi = 0; mi < 2; mi++)
#pragma unroll
            for (int j = 0; j < 8; j++) {
                int col = wn * 64 + j * 8 + tg * 2;
                float2 b2v = *(const float2*)(B2 + col);
                float2 fv  = *(const float2*)(&g_gfac[slot][col]);
                int r = mrow + mi * 16 + g;
                float* hp = &s_h[r * LDH + col];
                hp[0] += 0.5f * (zacc[mi][j][0] + b2v.x) * fv.x;
                hp[1] += 0.5f * (zacc[mi][j][1] + b2v.y) * fv.y;
                float* hp2 = &s_h[(r + 8) * LDH + col];
                hp2[0] += 0.5f * (zacc[mi][j][2] + b2v.x) * fv.x;
                hp2[1] += 0.5f * (zacc[mi][j][3] + b2v.y) * fv.y;
            }
        __syncthreads();
    }

    // ============================ classifier + emit ============================
    {
        float2 cw[4];
#pragma unroll
        for (int ci = 0; ci < 4; ci++)
            cw[ci] = *(const float2*)(cls_w + (lane * 4 + ci) * 2);
        float cb0 = cls_b[0], cb1 = cls_b[1];
#pragma unroll 4
        for (int rr = 0; rr < 16; rr++) {
            int r = wid * 16 + rr;
            float4 v = *(const float4*)&s_h[r * LDH + lane * 4];
            float a0 = v.x * cw[0].x + v.y * cw[1].x + v.z * cw[2].x + v.w * cw[3].x;
            float a1 = v.x * cw[0].y + v.y * cw[1].y + v.z * cw[2].y + v.w * cw[3].y;
#pragma unroll
            for (int o = 16; o > 0; o >>= 1) {
                a0 += __shfl_xor_sync(0xffffffffu, a0, o);
                a1 += __shfl_xor_sync(0xffffffffu, a1, o);
            }
            if (lane == 0) {
                size_t row = row0 + r;
                out[row * 2]     = a0 + cb0;
                out[row * 2 + 1] = a1 + cb1;
            }
        }
        // h output
        for (int i = tid; i < ROWS * 32; i += 256) {
            int r = i >> 5, c = (i & 31) * 4;
            *(float4*)&out[(size_t)B_TOTAL * 2 + (row0 + r) * DIM + c] =
                *(const float4*)&s_h[r * LDH + c];
        }
    }
}

// ---------------------------------------------------------------------------
extern "C" void kernel_launch(void* const* d_in, const int* in_sizes, int n_in,
                              void* d_out, int out_size) {
    const float* x      = (const float*)d_in[0];
    const float* proj_w = (const float*)d_in[1];
    const float* proj_b = (const float*)d_in[2];
    const float* pos    = (const float*)d_in[3];
    const float* sel_w  = (const float*)d_in[4];
    const float* sel_b  = (const float*)d_in[5];
    const float* ln_s   = (const float*)d_in[6];
    const float* ln_b   = (const float*)d_in[7];
    const float* w1     = (const float*)d_in[8];
    const float* b1     = (const float*)d_in[9];
    const float* w2     = (const float*)d_in[10];
    const float* b2     = (const float*)d_in[11];
    const float* gate   = (const float*)d_in[12];
    const float* cls_w  = (const float*)d_in[13];
    const float* cls_b  = (const float*)d_in[14];
    const float* tf     = (const float*)d_in[15];
    float* out = (float*)d_out;

    const int smem_bytes = (3 * ROWS * LDH + 4608) * sizeof(float);  // 221184 B
    cudaFuncSetAttribute(fused_kernel, cudaFuncAttributeMaxDynamicSharedMemorySize, smem_bytes);

    pilot_kernel<<<1, 256>>>(x, proj_w, proj_b, pos, sel_w, sel_b, ln_s, ln_b,
                             w1, b1, w2, b2, gate, tf);
    fused_kernel<<<B_TOTAL / ROWS, 256, smem_bytes>>>(
        x, proj_w, proj_b, pos, ln_s, ln_b, w1, b1, w2, b2, cls_w, cls_b, out);
}